// round 15
// baseline (speedup 1.0000x reference)
#include <cuda_runtime.h>
#include <cuda_fp16.h>
#include <cstdint>

#define NTREES 256
#define NPT    1024
#define NN     (NTREES * NPT)          // 262144 nodes
#define VOCAB  5000
#define SORTV  64
#define NPOS   1024
#define TCOLS  512                     // 384 iou cols + 128 f cols
#define BM     64
#define PAD2   68                      // padded row stride in uint32 (half2) words

// smem: sHL[64*68], sHR[64*68] packed half2 words
#define SMEMSZ  (2 * 64 * PAD2 * 4)    // 34816 bytes

// Device-global scratch (allocation-free per harness rules)
__device__ unsigned g_hH[NN * 64];     // h in fp16 pairs (64 MB)
__device__ float    g_c[NN * 128];     // c in fp32 (128 MB)
__device__ __half   g_Ttok[VOCAB * TCOLS];   // fp16 tables (6.5 MB total)
__device__ __half   g_Tsort[SORTV * TCOLS];
__device__ __half   g_Tpos[NPOS * TCOLS];
__device__ unsigned g_Upk[64 * 8 * 64];   // fp16 B frags: [nf(64)][ks16(8)][64 words]
__device__ int      g_is64;

__device__ __forceinline__ float tanha(float x) {
    float r;
    asm("tanh.approx.f32 %0, %1;" : "=f"(r) : "f"(x));
    return r;
}
__device__ __forceinline__ float sigf(float x) {
    return fmaf(0.5f, tanha(0.5f * x), 0.5f);
}
__device__ __forceinline__ unsigned packh2(float a, float b) {
    __half2 h = __floats2half2_rn(a, b);
    return *(unsigned*)&h;
}
__device__ __forceinline__ unsigned addh2(unsigned a, unsigned b) {
    __half2 r = __hadd2(*(__half2*)&a, *(__half2*)&b);
    return *(unsigned*)&r;
}
__device__ __forceinline__ float2 tbl3v2(const __half* t, const __half* s, const __half* p) {
    float2 a = __half22float2(*(const __half2*)t);
    float2 b = __half22float2(*(const __half2*)s);
    float2 c = __half22float2(*(const __half2*)p);
    return make_float2(a.x + b.x + c.x, a.y + b.y + c.y);
}
__device__ __forceinline__ float4 tbl3v4(const __half* t, const __half* s, const __half* p) {
    uint2 wa = *(const uint2*)t, wb = *(const uint2*)s, wc = *(const uint2*)p;
    float2 a0 = __half22float2(*(__half2*)&wa.x), a1 = __half22float2(*(__half2*)&wa.y);
    float2 b0 = __half22float2(*(__half2*)&wb.x), b1 = __half22float2(*(__half2*)&wb.y);
    float2 c0 = __half22float2(*(__half2*)&wc.x), c1 = __half22float2(*(__half2*)&wc.y);
    return make_float4(a0.x + b0.x + c0.x, a0.y + b0.y + c0.y,
                       a1.x + b1.x + c1.x, a1.y + b1.y + c1.y);
}

#define MMA16(ACC, A0, A1, A2, A3, B)                                          \
    asm volatile(                                                              \
        "mma.sync.aligned.m16n8k16.row.col.f32.f16.f16.f32 "                   \
        "{%0,%1,%2,%3}, {%4,%5,%6,%7}, {%8,%9}, {%0,%1,%2,%3};\n"              \
        : "+f"(ACC[0]), "+f"(ACC[1]), "+f"(ACC[2]), "+f"(ACC[3])               \
        : "r"(A0), "r"(A1), "r"(A2), "r"(A3), "r"(B.x), "r"(B.y))

// ldmatrix x4: loads a0..a3 of one 16x16 f16 A tile.
__device__ __forceinline__ void ldsm4(unsigned& d0, unsigned& d1,
                                      unsigned& d2, unsigned& d3, uint32_t addr)
{
    asm volatile("ldmatrix.sync.aligned.m8n8.x4.shared.b16 {%0,%1,%2,%3}, [%4];"
                 : "=r"(d0), "=r"(d1), "=r"(d2), "=r"(d3) : "r"(addr));
}

__device__ __forceinline__ int3 getfeat(const void* f, int g)
{
    if (g_is64) {
        const long long* p = (const long long*)f;
        return make_int3((int)p[3 * g], (int)p[3 * g + 1], (int)p[3 * g + 2]);
    }
    const int* p = (const int*)f;
    return make_int3(p[3 * g], p[3 * g + 1], p[3 * g + 2]);
}

// ---------------------------------------------------------------------------
// K0a (fused): blocks 0..127 pack U fragments (256 thr); block 128 dtype
// detect.
// ---------------------------------------------------------------------------
__global__ void k0a_pack_detect(const float* __restrict__ Uiou,
                                const float* __restrict__ Uf,
                                const int* __restrict__ featsw)
{
    int b = blockIdx.x;
    int j = threadIdx.x;

    if (b == 128) {
        if (j < 32) {
            unsigned any = __ballot_sync(0xffffffffu, featsw[j * 2 + 1] != 0);
            if (j == 0) g_is64 = (any == 0u) ? 1 : 0;
        }
        return;
    }

    int idx = b * 256 + j;             // 0..32767
    int f = idx >> 6, w = idx & 63;
    int nf = f >> 3, ks16 = f & 7;
    int lane = w >> 1, sel = w & 1;
    int kb = ks16 * 16 + 2 * (lane & 3) + 8 * sel;
    int c = lane >> 2;
    float lo, hi;
    if (nf < 48) {
        lo = Uiou[kb * 384 + nf * 8 + c];
        hi = Uiou[(kb + 1) * 384 + nf * 8 + c];
    } else {
        lo = Uf[kb * 128 + (nf - 48) * 8 + c];
        hi = Uf[(kb + 1) * 128 + (nf - 48) * 8 + c];
    }
    g_Upk[idx] = packh2(lo, hi);
}

// ---------------------------------------------------------------------------
// K0: projection tables in fp16.
// ---------------------------------------------------------------------------
__global__ void k0_tables(const float* __restrict__ emb,
                          const float* __restrict__ sortt,
                          const float* __restrict__ pe,
                          const float* __restrict__ Wiou,
                          const float* __restrict__ Wf,
                          const float* __restrict__ biou,
                          const float* __restrict__ bf)
{
    __shared__ float se[8][64];
    int b = blockIdx.x;
    int j = threadIdx.x;

    const float* src; int wbase; __half* dst; bool addb;
    if (b < 625)      { int r0 = b * 8;         src = emb   + r0 * 64; wbase = 0;   dst = g_Ttok  + r0 * TCOLS; addb = false; }
    else if (b < 633) { int r0 = (b - 625) * 8; src = sortt + r0 * 64; wbase = 64;  dst = g_Tsort + r0 * TCOLS; addb = false; }
    else              { int r0 = (b - 633) * 8; src = pe    + r0 * 64; wbase = 128; dst = g_Tpos  + r0 * TCOLS; addb = true;  }

    se[j >> 6][j & 63] = src[j];
    __syncthreads();

    float acc[8];
#pragma unroll
    for (int r = 0; r < 8; r++) acc[r] = 0.0f;

    float bias = 0.0f;
    if (j < 384) {
#pragma unroll 8
        for (int k = 0; k < 64; k++) {
            float w = Wiou[(wbase + k) * 384 + j];
#pragma unroll
            for (int r = 0; r < 8; r++) acc[r] += se[r][k] * w;
        }
        if (addb) bias = biou[j];
    } else {
        int jj = j - 384;
#pragma unroll 8
        for (int k = 0; k < 64; k++) {
            float w = Wf[(wbase + k) * 128 + jj];
#pragma unroll
            for (int r = 0; r < 8; r++) acc[r] += se[r][k] * w;
        }
        if (addb) bias = bf[jj];
    }
#pragma unroll
    for (int r = 0; r < 8; r++) dst[r * TCOLS + j] = __float2half(acc[r] + bias);
}

// ---------------------------------------------------------------------------
// K1: leaves.
// ---------------------------------------------------------------------------
__global__ void k1_leaves(const void* __restrict__ feats)
{
    int tid = threadIdx.x;
    int q   = tid & 31;
    int L   = blockIdx.x * 8 + (tid >> 5);
    int t   = L >> 9;
    int i   = 512 + (L & 511);
    int g   = t * NPT + i;

    int3 ft = getfeat(feats, g);

    const __half* Pt = g_Ttok  + ft.x * TCOLS + q * 4;
    const __half* Ps = g_Tsort + ft.y * TCOLS + q * 4;
    const __half* Pp = g_Tpos  + ft.z * TCOLS + q * 4;

    float4 pi = tbl3v4(Pt,       Ps,       Pp);
    float4 po = tbl3v4(Pt + 128, Ps + 128, Pp + 128);
    float4 pu = tbl3v4(Pt + 256, Ps + 256, Pp + 256);

    float4 cv = make_float4(sigf(pi.x) * tanha(pu.x), sigf(pi.y) * tanha(pu.y),
                            sigf(pi.z) * tanha(pu.z), sigf(pi.w) * tanha(pu.w));
    float4 hv = make_float4(sigf(po.x) * tanha(cv.x), sigf(po.y) * tanha(cv.y),
                            sigf(po.z) * tanha(cv.z), sigf(po.w) * tanha(cv.w));
    *(float4*)&g_c[g * 128 + q * 4] = cv;
    uint2 hw = make_uint2(packh2(hv.x, hv.y), packh2(hv.z, hv.w));
    *(uint2*)&g_hH[g * 64 + q * 2] = hw;
}

// B fragment load helper
#define LDB(NF, KS, V) \
    V = *(const uint2*)&g_Upk[(((NF)) * 8 + (KS)) * 64 + 2 * lane]

// ---------------------------------------------------------------------------
// K2: persistent kernel, 2 trees per block, 512 threads (16 warps), one
// block per SM. Warp w owns column group cg = w. Levels fuse both trees'
// node lists.
// ---------------------------------------------------------------------------
__global__ __launch_bounds__(512, 1) void k2_tree(
    const void* __restrict__ feats,
    float* __restrict__ out)
{
    extern __shared__ unsigned smu[];
    unsigned* sHL = smu;
    unsigned* sHR = smu + 64 * PAD2;

    __shared__ int sg[BM], sgl[BM], sgr[BM], stok[BM], ssrt[BM], spos[BM];

    int tid  = threadIdx.x;
    int lane = tid & 31;
    int w    = tid >> 5;               // warp 0..15 = column group
    int g4   = lane >> 2, tg = lane & 3;
    int t0   = blockIdx.x * 2;         // first tree of this block

    // ldmatrix per-lane address: row = lane&15, col-half = lane>>4
    uint32_t smbase = (uint32_t)__cvta_generic_to_shared(smu);
    uint32_t lmoff  = (((lane & 15) * PAD2) + (lane >> 4) * 4) * 4;
    uint32_t lmL    = smbase + lmoff;
    uint32_t lmR    = smbase + 64 * PAD2 * 4 + lmoff;

    // Prime B pipeline (ks=0); cg = w is constant for the whole kernel.
    uint2 Bi, Bo, Bu, Bf;
    LDB(w,      0, Bi);
    LDB(16 + w, 0, Bo);
    LDB(32 + w, 0, Bu);
    LDB(48 + w, 0, Bf);

    for (int l = 1; l <= 10; l++) {
        int cnt = (l == 1) ? 1 : (1 << (10 - l));   // nodes per tree at this level
        int beg = (l == 1) ? 511 : cnt - 1;
        int tot = 2 * cnt;                          // fused over both trees

        for (int ch = 0; ch < tot; ch += BM) {
            int n = tot - ch; if (n > BM) n = BM;   // valid rows this chunk

            __syncthreads();   // protect index arrays from prior chunk readers
            if (tid < BM) {
                int m = ch + ((tid < n) ? tid : 0); // clamp padding rows
                int tt = m / cnt;                   // 0 or 1: which tree
                int i  = beg + m % cnt;
                int tb = (t0 + tt) * NPT;
                int g  = tb + i;
                sg[tid]  = g;
                sgl[tid] = tb + 2 * i + 1;
                int rr2 = 2 * i + 2;
                sgr[tid] = (rr2 < NPT) ? tb + rr2 : -1;   // node 511: single child
                int3 ft = getfeat(feats, g);
                stok[tid] = ft.x;
                ssrt[tid] = ft.y;
                spos[tid] = ft.z;
            }
            __syncthreads();

            // Stage child h tiles (fp16 pair words): 1024 uint4 slots, 512 thr
#pragma unroll
            for (int r2 = 0; r2 < 2; r2++) {
                int idx = tid + r2 * 512;          // = m*16 + q
                int m = idx >> 4, q = idx & 15;
                uint4 hl = *(const uint4*)&g_hH[sgl[m] * 64 + q * 4];
                uint4 hr = make_uint4(0u, 0u, 0u, 0u);
                int gr = sgr[m];
                if (gr >= 0) hr = *(const uint4*)&g_hH[gr * 64 + q * 4];
                *(uint4*)&sHL[m * PAD2 + q * 4] = hl;
                *(uint4*)&sHR[m * PAD2 + q * 4] = hr;
            }
            __syncthreads();

            // Each warp: its 8 columns (cg=w), all 4 m-tiles, all 8 ks.
            float accI[4][4], accO[4][4], accU[4][4], accFL[4][4], accFR[4][4];
#pragma unroll
            for (int mt = 0; mt < 4; mt++)
#pragma unroll
                for (int e = 0; e < 4; e++) {
                    accI[mt][e] = accO[mt][e] = accU[mt][e] = 0.0f;
                    accFL[mt][e] = accFR[mt][e] = 0.0f;
                }

#pragma unroll 1
            for (int ks = 0; ks < 8; ks++) {
                int nks = (ks + 1) & 7;            // cyclic prefetch (next chunk wraps)
                uint2 Ni, No, Nu, Nf;
                LDB(w,      nks, Ni);
                LDB(16 + w, nks, No);
                LDB(32 + w, nks, Nu);
                LDB(48 + w, nks, Nf);

#pragma unroll
                for (int mt = 0; mt < 4; mt++) {
                    if (mt * 16 < n) {
                        uint32_t toff = (mt * 16 * PAD2 + 8 * ks) * 4;
                        unsigned l0, l1, l2, l3, r0, r1, r2, r3;
                        ldsm4(l0, l1, l2, l3, lmL + toff);
                        ldsm4(r0, r1, r2, r3, lmR + toff);
                        unsigned s0 = addh2(l0, r0), s1 = addh2(l1, r1);
                        unsigned s2 = addh2(l2, r2), s3 = addh2(l3, r3);
                        MMA16(accI[mt], s0, s1, s2, s3, Bi);
                        MMA16(accO[mt], s0, s1, s2, s3, Bo);
                        MMA16(accU[mt], s0, s1, s2, s3, Bu);
                        MMA16(accFL[mt], l0, l1, l2, l3, Bf);
                        MMA16(accFR[mt], r0, r1, r2, r3, Bf);
                    }
                }
                Bi = Ni; Bo = No; Bu = Nu; Bf = Nf;
            }

            // Register epilogue: rows m = mt*16 + rr*8 + g4, cols c0, c0+1.
            int c0 = w * 8 + 2 * tg;
#pragma unroll
            for (int mt = 0; mt < 4; mt++)
#pragma unroll
                for (int rr = 0; rr < 2; rr++) {
                    int m = mt * 16 + rr * 8 + g4;
                    if (m >= n) continue;
                    int a = rr * 2;
                    const __half* Tt = g_Ttok  + stok[m] * TCOLS + c0;
                    const __half* Ts = g_Tsort + ssrt[m] * TCOLS + c0;
                    const __half* Tp = g_Tpos  + spos[m] * TCOLS + c0;

                    float2 pi = tbl3v2(Tt,       Ts,       Tp);
                    float2 po = tbl3v2(Tt + 128, Ts + 128, Tp + 128);
                    float2 pu = tbl3v2(Tt + 256, Ts + 256, Tp + 256);
                    float2 pf = tbl3v2(Tt + 384, Ts + 384, Tp + 384);

                    float2 cl = *(const float2*)&g_c[sgl[m] * 128 + c0];
                    float2 cr = make_float2(0.f, 0.f);
                    int gr = sgr[m];
                    if (gr >= 0) cr = *(const float2*)&g_c[gr * 128 + c0];

                    float cx = sigf(accI[mt][a]   + pi.x) * tanha(accU[mt][a]   + pu.x)
                             + sigf(accFL[mt][a]  + pf.x) * cl.x
                             + sigf(accFR[mt][a]  + pf.x) * cr.x;
                    float cy = sigf(accI[mt][a+1] + pi.y) * tanha(accU[mt][a+1] + pu.y)
                             + sigf(accFL[mt][a+1] + pf.y) * cl.y
                             + sigf(accFR[mt][a+1] + pf.y) * cr.y;
                    float hx = sigf(accO[mt][a]   + po.x) * tanha(cx);
                    float hy = sigf(accO[mt][a+1] + po.y) * tanha(cy);

                    int gg = sg[m];
                    *(float2*)&g_c[gg * 128 + c0] = make_float2(cx, cy);
                    g_hH[gg * 64 + (c0 >> 1)] = packh2(hx, hy);
                    if (l == 10)
                        *(float2*)&out[(gg >> 10) * 128 + c0] = make_float2(hx, hy);
                }
        }
    }
}

// ---------------------------------------------------------------------------
extern "C" void kernel_launch(void* const* d_in, const int* in_sizes, int n_in,
                              void* d_out, int out_size)
{
    const void* feats  = d_in[0];
    const float* emb   = (const float*)d_in[4];
    const float* sortt = (const float*)d_in[5];
    const float* pe    = (const float*)d_in[6];
    const float* Wiou  = (const float*)d_in[7];
    const float* Uiou  = (const float*)d_in[8];
    const float* biou  = (const float*)d_in[9];
    const float* Wf    = (const float*)d_in[10];
    const float* Uf    = (const float*)d_in[11];
    const float* bf    = (const float*)d_in[12];
    float* out = (float*)d_out;

    cudaFuncSetAttribute(k2_tree, cudaFuncAttributeMaxDynamicSharedMemorySize, SMEMSZ);

    k0a_pack_detect<<<129, 256>>>(Uiou, Uf, (const int*)feats);
    k0_tables<<<761, 512>>>(emb, sortt, pe, Wiou, Wf, biou, bf);
    k1_leaves<<<16384, 256>>>(feats);

    // 2 trees per block, 128 blocks (one wave, uniform load).
    k2_tree<<<NTREES / 2, 512, SMEMSZ>>>(feats, out);
}